// round 17
// baseline (speedup 1.0000x reference)
#include <cuda_runtime.h>
#include <stdint.h>

#define COLA 528                 // A row stride (bytes)
#define COLB 544                 // B col stride (bytes)
#define ASZ (128 * COLA)         // 67584
#define BSZ (64 * COLB)          // 34816
#define W16SZ (256 * 64 * 4)     // 65536 : [kpair][64 cols] u32 (s16x2)

// SMEM: sA | B1 | B2 | W16 | bb(136w) | corr
#define SB1_OFF  (ASZ)                   // 67584
#define SB2_OFF  (ASZ + BSZ)             // 102400
#define SW_OFF   (ASZ + 2 * BSZ)         // 137216
#define BB_OFF   (SW_OFF + W16SZ)        // 202752
#define CORR_OFF (BB_OFF + 544)          // 203296
#define SMEM_DYN (CORR_OFF + 256)        // 203552

static __device__ __align__(16) signed char g_Wd1[BSZ];
static __device__ __align__(16) signed char g_Wd2[BSZ];
static __device__ __align__(16) uint32_t    g_W16[256 * 64];
static __device__ float g_corr[64];
static __device__ float g_sc;
static __device__ int   g_stride;

// ---------------------------------------------------------------------------
__device__ __forceinline__ void imma(int* c, uint32_t a0, uint32_t a1,
                                     uint32_t a2, uint32_t a3,
                                     uint32_t b0, uint32_t b1) {
    asm volatile(
        "mma.sync.aligned.m16n8k32.row.col.s32.s8.s8.s32 "
        "{%0,%1,%2,%3}, {%4,%5,%6,%7}, {%8,%9}, {%0,%1,%2,%3};"
        : "+r"(c[0]), "+r"(c[1]), "+r"(c[2]), "+r"(c[3])
        : "r"(a0), "r"(a1), "r"(a2), "r"(a3), "r"(b0), "r"(b1));
}

// ---------------------------------------------------------------------------
// Prep (R7-validated): two s8 digits in fragment order, packed s16 weights,
// column sums, input-width detection.
// ---------------------------------------------------------------------------
static __global__ void bf_prep(const float* __restrict__ W,
                               const uint32_t* __restrict__ xw)
{
    __shared__ float red[512];
    int o = blockIdx.x, k = threadIdx.x;

    if (o == 0 && k == 0) {
        uint32_t acc = 0;
        for (int j = 1; j < 256; j += 2) acc |= xw[j];
        g_stride = (acc == 0u) ? 2 : 1;
    }

    float mx = 0.f;
    for (int i = k; i < 496 * 64; i += 512) mx = fmaxf(mx, fabsf(W[i]));
    red[k] = mx;
    __syncthreads();
    for (int d = 256; d; d >>= 1) {
        if (k < d) red[k] = fmaxf(red[k], red[k + d]);
        __syncthreads();
    }
    float maxabs = fmaxf(red[0], 1e-30f);
    __syncthreads();

    float s1 = maxabs * (1.0f / 127.0f), inv1 = 127.0f / maxabs;
    float inv2 = 128.0f / s1;

    float w = (k < 496) ? W[k * 64 + o] : 0.f;
    int d1 = __float2int_rn(w * inv1);
    d1 = max(-127, min(127, d1));
    float r = w - s1 * (float)d1;
    int d2 = __float2int_rn(r * inv2);           // in [-64, 64]

    int ks = k >> 5, wrd = (k >> 2) & 7, tig = wrd & 3, hf = wrd >> 2, by = k & 3;
    int addr = o * COLB + ks * 32 + tig * 8 + hf * 4 + by;
    g_Wd1[addr] = (signed char)d1;
    g_Wd2[addr] = (signed char)d2;

    // packed s16 weight for the dp2a path: w16 = 128*d1 + d2, [kpair][col]
    ((short*)g_W16)[((k >> 1) * 64 + o) * 2 + (k & 1)] = (short)((d1 << 7) + d2);

    red[k] = w;
    __syncthreads();
    for (int d = 256; d; d >>= 1) {
        if (k < d) red[k] += red[k + d];
        __syncthreads();
    }
    if (k == 0) {
        g_corr[o] = red[0] * (1.0f / 255.0f);
        if (o == 0) g_sc = (2.0f / 255.0f) * s1 * (1.0f / 128.0f);
    }
}

// ---------------------------------------------------------------------------
// Hybrid persistent kernel: grid 148 x 512, 1 CTA/SM.
// All threads build A (1 task each). Compute: warps 0-3 = tensor IMMA
// (rows 0-63, two s8 digit passes); warps 4-11 = dp2a (rows 64-127, single
// s16 pass, broadcast-clean operand layout); warps 12-15 idle in compute.
// ---------------------------------------------------------------------------
static __global__ void __launch_bounds__(512, 1)
bf_main(const uint32_t* __restrict__ xw, float* __restrict__ out)
{
    extern __shared__ __align__(16) char sm[];
    char*      sA    = sm;
    char*      sB1   = sm + SB1_OFF;
    char*      sB2   = sm + SB2_OFF;
    char*      sW    = sm + SW_OFF;
    uint32_t*  bb    = (uint32_t*)(sm + BB_OFF);
    float*     scorr = (float*)(sm + CORR_OFF);

    const int t = threadIdx.x, lane = t & 31, wid = t >> 5;
    const int stride = g_stride;
    const float sc = g_sc;
    const int n0 = blockIdx.x;

    // ---- prologue: copy B digits + W16 + corr, zero byte pad, first bytes ----
    {
        const uint4* w1 = (const uint4*)g_Wd1;
        const uint4* w2 = (const uint4*)g_Wd2;
        const uint4* w3 = (const uint4*)g_W16;
        uint4* p1 = (uint4*)sB1;
        uint4* p2 = (uint4*)sB2;
        uint4* p3 = (uint4*)sW;
        for (int i = t; i < BSZ / 16; i += 512) { p1[i] = w1[i]; p2[i] = w2[i]; }
        for (int i = t; i < W16SZ / 16; i += 512) p3[i] = w3[i];
        if (t < 64) scorr[t] = g_corr[t];
        if (t < 8)  bb[128 + t] = 0u;
        ((unsigned char*)bb)[t] = (unsigned char)xw[((size_t)n0 * 512 + t) * (size_t)stride];
    }
    uint32_t breg;
    {
        int nb = n0 + 148; if (nb > 2047) nb = 2047;
        breg = xw[((size_t)nb * 512 + t) * (size_t)stride];
    }

    // ---- invariants: A build (row t>>2, quarter t&3) ----
    const int r = t >> 2, q = t & 3;
    const int g = r >> 3, s = r & 7;
    const int g4 = g >> 2, gr = g & 3;
    const uint32_t sel0 = 0x3210u + 0x1111u * (uint32_t)gr;
    const uint32_t sel1 = sel0 + 0x1111u;
    const uint32_t M1 = 0x01010101u * ((0xFFu << s) & 0xFFu);
    const uint32_t M2 = 0x01010101u * (0xFFu >> (8 - s));
    char* rowp = sA + r * COLA + q * 128;

    // ---- invariants: tensor warps (wid 0-3, rows 0-63) ----
    const int gid = lane >> 2, tig = lane & 3;
    const int aOff = wid * 16 * COLA + gid * COLA + 4 * tig;
    const int row0 = wid * 16 + gid;
    int bCol[8];
    #pragma unroll
    for (int nt = 0; nt < 8; nt++) bCol[nt] = (nt * 8 + gid) * COLB + tig * 8;

    // ---- invariants: dp2a warps (wid 4-11, rows 64-127) ----
    const int dw = wid - 4;                        // 0..7
    const int drow = 64 + dw * 8 + (lane >> 2);    // this thread's row
    const int cg = lane & 3;                       // 16-col group
    const char* aP = sA + drow * COLA;
    const char* wP = sW + cg * 64;

    __syncthreads();

    float corr0[8], corr1[8];
    #pragma unroll
    for (int nt = 0; nt < 8; nt++) {
        int col = nt * 8 + 2 * tig;
        corr0[nt] = scorr[col];
        corr1[nt] = scorr[col + 1];
    }
    float dcorr[16];
    #pragma unroll
    for (int j = 0; j < 16; j++) dcorr[j] = scorr[cg * 16 + j];

    for (int n = n0; n < 2048; n += 148) {
        // ---- build A (all 512 threads, 1 task each) ----
        #pragma unroll
        for (int m = 0; m < 8; m++) {
            int wbase = q * 32 + m * 4;
            uint32_t A0 = bb[wbase + g4];
            uint32_t acc[4];
            #pragma unroll
            for (int j = 0; j < 4; j++) {
                uint32_t B0 = bb[wbase + g4 + j + 1];
                uint32_t X = __byte_perm(A0, B0, sel0);
                uint32_t Y = __byte_perm(A0, B0, sel1);
                acc[j] = (((X << s) & M1) | ((Y >> (8 - s)) & M2)) ^ 0x80808080u;
                A0 = B0;
            }
            *(uint4*)(rowp + m * 16) = make_uint4(acc[0], acc[1], acc[2], acc[3]);
        }
        __syncthreads();                 // A ready; bb reads (build) done

        // ---- recycle byte buffer during compute ----
        ((unsigned char*)bb)[t] = (unsigned char)breg;
        {
            int nb = n + 296; if (nb > 2047) nb = 2047;
            breg = xw[((size_t)nb * 512 + t) * (size_t)stride];
        }

        if (wid < 4) {
            // ================= TENSOR: rows 0-63, two s8 digit passes ======
            int c1[32], c2[32];
            #pragma unroll
            for (int j = 0; j < 32; j++) { c1[j] = 0; c2[j] = 0; }

            const char* aR = sA + aOff;
            #pragma unroll
            for (int ks = 0; ks < 16; ks++) {
                int k0 = ks * 32;
                uint32_t a0 = *(const uint32_t*)(aR + k0);
                uint32_t a2 = *(const uint32_t*)(aR + k0 + 16);
                uint32_t a1 = *(const uint32_t*)(aR + 8 * COLA + k0);
                uint32_t a3 = *(const uint32_t*)(aR + 8 * COLA + k0 + 16);
                #pragma unroll
                for (int nt = 0; nt < 8; nt++) {
                    uint2 b = *(const uint2*)(sB1 + bCol[nt] + k0);
                    imma(c1 + 4 * nt, a0, a1, a2, a3, b.x, b.y);
                    uint2 e = *(const uint2*)(sB2 + bCol[nt] + k0);
                    imma(c2 + 4 * nt, a0, a1, a2, a3, e.x, e.y);
                }
            }
            {
                float* po = out + (size_t)n * 8192;
                #pragma unroll
                for (int nt = 0; nt < 8; nt++) {
                    int col = nt * 8 + 2 * tig;
                    float2 v0, v1;
                    v0.x = fmaf(sc, (float)((c1[4*nt+0] << 7) + c2[4*nt+0]), corr0[nt]);
                    v0.y = fmaf(sc, (float)((c1[4*nt+1] << 7) + c2[4*nt+1]), corr1[nt]);
                    v1.x = fmaf(sc, (float)((c1[4*nt+2] << 7) + c2[4*nt+2]), corr0[nt]);
                    v1.y = fmaf(sc, (float)((c1[4*nt+3] << 7) + c2[4*nt+3]), corr1[nt]);
                    __stcs((float2*)(po + row0 * 64 + col), v0);
                    __stcs((float2*)(po + (row0 + 8) * 64 + col), v1);
                }
            }
        } else if (wid < 12) {
            // ================= DP2A: rows 64-127, single s16 pass ==========
            int acc[16];
            #pragma unroll
            for (int j = 0; j < 16; j++) acc[j] = 0;

            #pragma unroll 4
            for (int k4 = 0; k4 < 128; k4++) {
                uint32_t aw = *(const uint32_t*)(aP + k4 * 4);   // 4 bytes = 2 kp
                const char* w0 = wP + (size_t)(2 * k4) * 256;    // kp0: 16 cols
                uint4 wa = *(const uint4*)(w0);
                uint4 wb = *(const uint4*)(w0 + 16);
                uint4 wc = *(const uint4*)(w0 + 32);
                uint4 wd = *(const uint4*)(w0 + 48);
                acc[0]  = __dp2a_lo((int)wa.x, (int)aw, acc[0]);
                acc[1]  = __dp2a_lo((int)wa.y, (int)aw, acc[1]);
                acc[2]  = __dp2a_lo((int)wa.z, (int)aw, acc[2]);
                acc[3]  = __dp2a_lo((int)wa.w, (int)aw, acc[3]);
                acc[4]  = __dp2a_lo((int)wb.x, (int)aw, acc[4]);
                acc[5]  = __dp2a_lo((int)wb.y, (int)aw, acc[5]);
                acc[6]  = __dp2a_lo((int)wb.z, (int)aw, acc[6]);
                acc[7]  = __dp2a_lo((int)wb.w, (int)aw, acc[7]);
                acc[8]  = __dp2a_lo((int)wc.x, (int)aw, acc[8]);
                acc[9]  = __dp2a_lo((int)wc.y, (int)aw, acc[9]);
                acc[10] = __dp2a_lo((int)wc.z, (int)aw, acc[10]);
                acc[11] = __dp2a_lo((int)wc.w, (int)aw, acc[11]);
                acc[12] = __dp2a_lo((int)wd.x, (int)aw, acc[12]);
                acc[13] = __dp2a_lo((int)wd.y, (int)aw, acc[13]);
                acc[14] = __dp2a_lo((int)wd.z, (int)aw, acc[14]);
                acc[15] = __dp2a_lo((int)wd.w, (int)aw, acc[15]);
                const char* w1 = w0 + 256;                       // kp1
                wa = *(const uint4*)(w1);
                wb = *(const uint4*)(w1 + 16);
                wc = *(const uint4*)(w1 + 32);
                wd = *(const uint4*)(w1 + 48);
                acc[0]  = __dp2a_hi((int)wa.x, (int)aw, acc[0]);
                acc[1]  = __dp2a_hi((int)wa.y, (int)aw, acc[1]);
                acc[2]  = __dp2a_hi((int)wa.z, (int)aw, acc[2]);
                acc[3]  = __dp2a_hi((int)wa.w, (int)aw, acc[3]);
                acc[4]  = __dp2a_hi((int)wb.x, (int)aw, acc[4]);
                acc[5]  = __dp2a_hi((int)wb.y, (int)aw, acc[5]);
                acc[6]  = __dp2a_hi((int)wb.z, (int)aw, acc[6]);
                acc[7]  = __dp2a_hi((int)wb.w, (int)aw, acc[7]);
                acc[8]  = __dp2a_hi((int)wc.x, (int)aw, acc[8]);
                acc[9]  = __dp2a_hi((int)wc.y, (int)aw, acc[9]);
                acc[10] = __dp2a_hi((int)wc.z, (int)aw, acc[10]);
                acc[11] = __dp2a_hi((int)wc.w, (int)aw, acc[11]);
                acc[12] = __dp2a_hi((int)wd.x, (int)aw, acc[12]);
                acc[13] = __dp2a_hi((int)wd.y, (int)aw, acc[13]);
                acc[14] = __dp2a_hi((int)wd.z, (int)aw, acc[14]);
                acc[15] = __dp2a_hi((int)wd.w, (int)aw, acc[15]);
            }
            {
                float* po = out + (size_t)n * 8192 + (size_t)drow * 64 + cg * 16;
                float4 v;
                v.x = fmaf(sc, (float)acc[0],  dcorr[0]);
                v.y = fmaf(sc, (float)acc[1],  dcorr[1]);
                v.z = fmaf(sc, (float)acc[2],  dcorr[2]);
                v.w = fmaf(sc, (float)acc[3],  dcorr[3]);
                __stcs((float4*)(po), v);
                v.x = fmaf(sc, (float)acc[4],  dcorr[4]);
                v.y = fmaf(sc, (float)acc[5],  dcorr[5]);
                v.z = fmaf(sc, (float)acc[6],  dcorr[6]);
                v.w = fmaf(sc, (float)acc[7],  dcorr[7]);
                __stcs((float4*)(po + 4), v);
                v.x = fmaf(sc, (float)acc[8],  dcorr[8]);
                v.y = fmaf(sc, (float)acc[9],  dcorr[9]);
                v.z = fmaf(sc, (float)acc[10], dcorr[10]);
                v.w = fmaf(sc, (float)acc[11], dcorr[11]);
                __stcs((float4*)(po + 8), v);
                v.x = fmaf(sc, (float)acc[12], dcorr[12]);
                v.y = fmaf(sc, (float)acc[13], dcorr[13]);
                v.z = fmaf(sc, (float)acc[14], dcorr[14]);
                v.w = fmaf(sc, (float)acc[15], dcorr[15]);
                __stcs((float4*)(po + 12), v);
            }
        }
        __syncthreads();                 // bb committed; A reads done
    }
}

// ---------------------------------------------------------------------------
extern "C" void kernel_launch(void* const* d_in, const int* in_sizes, int n_in,
                              void* d_out, int out_size)
{
    const uint32_t* xw  = (const uint32_t*)d_in[0];
    const float*    W   = (const float*)d_in[1];
    float*          out = (float*)d_out;

    cudaFuncSetAttribute(bf_main, cudaFuncAttributeMaxDynamicSharedMemorySize, SMEM_DYN);
    bf_prep<<<64, 512>>>(W, xw);
    bf_main<<<148, 512, SMEM_DYN>>>(xw, out);
}